// round 9
// baseline (speedup 1.0000x reference)
#include <cuda_runtime.h>
#include <cstdint>

#define Bb 64
#define Hh 1024
#define Ss 512
#define THREADS 128
#define T_TILE 4
#define NTILES (Ss / T_TILE)     // 128

// smem: staging [1024][4] (16KB) + trans [4][1024] (16KB) + part [2][4][4] (128B)
#define STG_OFF   0
#define TRN_OFF   4096
#define PART_OFF  8192
#define SMEM_FLOATS (PART_OFF + 32 + 16)

__device__ __forceinline__ void cpa16(uint32_t dst, const float* src) {
    asm volatile("cp.async.cg.shared.global [%0], [%1], 16;\n" :: "r"(dst), "l"(src));
}

// One active scan step. sl is a compile-time literal via the macro expansion.
// Critical path: 12 FMA -> 3-chain butterfly -> STS/bar/LDS combine -> rsqrt -> update.
#define SCAN_STEP(SL, MVAL, PREFETCH_NEXT)                                      \
    do {                                                                        \
        if ((MVAL) != 0.0f) { /* mask uniform across the block */               \
            float sv[8] = {s0.x, s0.y, s0.z, s0.w, s1.x, s1.y, s1.z, s1.w};     \
            float d0 = 0.f, d1 = 0.f, q0 = 0.f, q1 = 0.f, r0 = 0.f, r1 = 0.f;   \
            _Pragma("unroll")                                                   \
            for (int i = 0; i < 4; i++) {                                       \
                d0 = fmaf(h[i],     sv[i],     d0);                             \
                d1 = fmaf(h[i + 4], sv[i + 4], d1);                             \
                q0 = fmaf(h[i],     h[i],      q0);                             \
                q1 = fmaf(h[i + 4], h[i + 4],  q1);                             \
                r0 = fmaf(sv[i],     sv[i],     r0);                            \
                r1 = fmaf(sv[i + 4], sv[i + 4], r1);                            \
            }                                                                   \
            float dot = d0 + d1, hh = q0 + q1, ssq = r0 + r1;                   \
            _Pragma("unroll")  /* 3 chains interleaved: levels overlap */       \
            for (int o = 16; o; o >>= 1) {                                      \
                float td = __shfl_xor_sync(0xffffffffu, dot, o);                \
                float th = __shfl_xor_sync(0xffffffffu, hh,  o);                \
                float ts = __shfl_xor_sync(0xffffffffu, ssq, o);                \
                dot += td; hh += th; ssq += ts;                                 \
            }                                                                   \
            if (SL != T_TILE - 1 && (PREFETCH_NEXT)) { /* before the bar */     \
                s0 = *(const float4*)(trans + (SL + 1) * Hh + tid * 4);         \
                s1 = *(const float4*)(trans + (SL + 1) * Hh + 512 + tid * 4);   \
            }                                                                   \
            if (lane == 0)                                                      \
                *(float4*)(part + pp * 16 + warp * 4)                           \
                    = make_float4(dot, hh, ssq, 0.f);                           \
            __syncthreads();                                                    \
            float4 w0 = *(const float4*)(part + pp * 16);                       \
            float4 w1 = *(const float4*)(part + pp * 16 + 4);                   \
            float4 w2 = *(const float4*)(part + pp * 16 + 8);                   \
            float4 w3 = *(const float4*)(part + pp * 16 + 12);                  \
            float D  = (w0.x + w1.x) + (w2.x + w3.x);                           \
            float HH = (w0.y + w1.y) + (w2.y + w3.y);                           \
            float SS = (w0.z + w1.z) + (w2.z + w3.z);                           \
            float ra = rsqrtf(fmaxf(HH, 1e-30f));                               \
            float rb = rsqrtf(fmaxf(SS, 1e-30f));                               \
            float a  = 1.0f - (D * ra) * rb;  /* h*(1-cos) + s */               \
            _Pragma("unroll")                                                   \
            for (int i = 0; i < 8; i++)                                         \
                h[i] = fminf(fmaxf(fmaf(h[i], a, sv[i]), -1.0f), 1.0f);         \
            pp ^= 1;                                                            \
        } else {                                                                \
            _Pragma("unroll")  /* reference clips even when mask == 0 */        \
            for (int i = 0; i < 8; i++)                                         \
                h[i] = fminf(fmaxf(h[i], -1.0f), 1.0f);                         \
            if (SL != T_TILE - 1 && (PREFETCH_NEXT)) {                          \
                s0 = *(const float4*)(trans + (SL + 1) * Hh + tid * 4);         \
                s1 = *(const float4*)(trans + (SL + 1) * Hh + 512 + tid * 4);   \
            }                                                                   \
        }                                                                       \
    } while (0)

// ---------------------------------------------------------------------------
// Single kernel: 64 CTAs, one per batch. No scratch, no pre-pass, no flags.
// Per 4-step tile: cp.async 16B/h-row straight from the ORIGINAL (B,H,S)
// layout (contiguous in s), smem-transpose to [s][h], scan.
// ---------------------------------------------------------------------------
__global__ __launch_bounds__(THREADS, 1)
void scan_kernel(const float* __restrict__ tree,
                 const float* __restrict__ seq,
                 const float* __restrict__ mask_in,
                 float* __restrict__ out) {
    __shared__ float sm[SMEM_FLOATS];
    float* staged = sm + STG_OFF;    // [1024 h-slots][4 s]
    float* trans  = sm + TRN_OFF;    // [4 s][1024 h]
    float* part   = sm + PART_OFF;   // [2][4 warps] float4 (dot,hh,ssq,-)

    const int tid  = threadIdx.x;
    const int b    = blockIdx.x;
    const int lane = tid & 31;
    const int warp = tid >> 5;
    const uint32_t stg_u32 = (uint32_t)__cvta_generic_to_shared(staged);
    const float* src_b = seq + (size_t)b * Hh * Ss;

    // Prologue: cp.async tile 0 (16B per h-row, 2KB-strided sources).
#pragma unroll
    for (int j = 0; j < 8; j++) {
        int slot = tid + 128 * j;
        cpa16(stg_u32 + slot * 16, src_b + (size_t)slot * Ss);
    }
    asm volatile("cp.async.commit_group;\n");

    // h state: thread owns h = {4*tid+k, 512+4*tid+k}, k=0..3
    float h[8];
    {
        float4 a = *(const float4*)(tree + b * Hh + tid * 4);
        float4 c = *(const float4*)(tree + b * Hh + 512 + tid * 4);
        h[0]=a.x; h[1]=a.y; h[2]=a.z; h[3]=a.w;
        h[4]=c.x; h[5]=c.y; h[6]=c.z; h[7]=c.w;
    }

    int pp = 0;
    for (int k = 0; k < NTILES; k++) {
        asm volatile("cp.async.wait_group 0;\n" ::: "memory");
        __syncthreads();                      // staged(k) visible; trans reads of k-1 done

        // Mask for this tile: one broadcast LDG.128, hidden under the transpose.
        float4 m4 = *(const float4*)(mask_in + b * Ss + k * 4);

        // In-CTA transpose staged[h][4] -> trans[s][h].
        // 8x contiguous LDS.128 + 32x conflict-free STS.32 per thread.
#pragma unroll
        for (int j = 0; j < 8; j++) {
            int slot = tid + 128 * j;
            float4 v = *(const float4*)(staged + slot * 4);
            trans[slot]            = v.x;
            trans[Hh + slot]       = v.y;
            trans[2 * Hh + slot]   = v.z;
            trans[3 * Hh + slot]   = v.w;
        }
        __syncthreads();                      // trans visible; staged free

        // Issue next tile's strided loads (has ~4 steps to land).
        if (k + 1 < NTILES) {
            const float* srcn = src_b + (k + 1) * T_TILE;
#pragma unroll
            for (int j = 0; j < 8; j++) {
                int slot = tid + 128 * j;
                cpa16(stg_u32 + slot * 16, srcn + (size_t)slot * Ss);
            }
            asm volatile("cp.async.commit_group;\n");
        }

        // 4 unrolled steps; s prefetched one step ahead across the combine bar.
        float4 s0 = *(const float4*)(trans + tid * 4);
        float4 s1 = *(const float4*)(trans + 512 + tid * 4);
        SCAN_STEP(0, m4.x, 1);
        SCAN_STEP(1, m4.y, 1);
        SCAN_STEP(2, m4.z, 1);
        SCAN_STEP(3, m4.w, 0);
    }

    float* o = out + b * Hh;
    *(float4*)(o + tid * 4)       = make_float4(h[0], h[1], h[2], h[3]);
    *(float4*)(o + 512 + tid * 4) = make_float4(h[4], h[5], h[6], h[7]);
}

// ---------------------------------------------------------------------------
extern "C" void kernel_launch(void* const* d_in, const int* in_sizes, int n_in,
                              void* d_out, int out_size) {
    const float* tree = (const float*)d_in[0];   // (B,H)
    const float* seq  = (const float*)d_in[1];   // (B,H,S)
    const float* mask = (const float*)d_in[2];   // (B,S)
    float* out = (float*)d_out;                  // (B,H)

    scan_kernel<<<Bb, THREADS>>>(tree, seq, mask, out);
}

// round 10
// speedup vs baseline: 1.2558x; 1.2558x over previous
#include <cuda_runtime.h>
#include <cstdint>

#define Bb 64
#define Hh 1024
#define Ss 512
#define THREADS 128
#define SCAN_CTAS Bb
#define NCHUNK 16                  // s-chunks of 32 steps
#define QUARTERS 4                 // h split per producer chunk
#define TR_CTAS (Bb * NCHUNK * QUARTERS)   // 4096

#define T_TILE 4
#define NTILES (Ss / T_TILE)       // 128
#define SB_FLOATS (2 * T_TILE * Hh)                 // 32 KB double buffer
#define SMEM_FLOATS (SB_FLOATS + (Ss + 8) + 32 + 16)

// Scratch: transposed seq [B][S][H]; norm partials [B][C][32][4]; flags [B*C].
__device__ float g_trans[(size_t)Bb * Ss * Hh];       // 128 MB
__device__ float g_ssp4[Bb * NCHUNK * 32 * QUARTERS]; // 512 KB
__device__ int   g_flag[Bb * NCHUNK];                 // arrive-count target = 4

__global__ void zero_flags_kernel() {
    int i = blockIdx.x * blockDim.x + threadIdx.x;
    if (i < Bb * NCHUNK) g_flag[i] = 0;
}

__device__ __forceinline__ void cpa16(uint32_t dst, const float* src) {
    asm volatile("cp.async.cg.shared.global [%0], [%1], 16;\n" :: "r"(dst), "l"(src));
}

__device__ __forceinline__ void wait_flag(int fi) {
    if (threadIdx.x == 0) {
        int v;
        asm volatile("ld.acquire.gpu.global.b32 %0, [%1];"
                     : "=r"(v) : "l"(g_flag + fi) : "memory");
        while (v < QUARTERS) {
            __nanosleep(64);
            asm volatile("ld.acquire.gpu.global.b32 %0, [%1];"
                         : "=r"(v) : "l"(g_flag + fi) : "memory");
        }
    }
    __syncthreads();
}

// ---------------------------------------------------------------------------
// bid 0..63   : scan CTA (batch b = bid)
// bid 64..    : producer CTA (b, chunk, quarter): transpose 32s x 256h
//               + 4-way h-partial of ||s||^2, then release the flag.
// ---------------------------------------------------------------------------
__global__ __launch_bounds__(THREADS, 1)
void fused_kernel(const float* __restrict__ tree,
                  const float* __restrict__ seq,
                  const float* __restrict__ mask_in,
                  float* __restrict__ out) {
    __shared__ float sm[SMEM_FLOATS];
    const int tid  = threadIdx.x;
    const int lane = tid & 31;
    const int warp = tid >> 5;

    if (blockIdx.x >= SCAN_CTAS) {
        // ======================= producer role =======================
        float (*tile)[33] = (float(*)[33])sm;     // 32x33 floats (4.2 KB)
        const int idx = blockIdx.x - SCAN_CTAS;   // chunk-major ordering
        const int q   = idx & 3;
        const int bc  = idx >> 2;                 // c*64 + b
        const int b   = bc & 63;
        const int c   = bc >> 6;
        const int s0  = c * 32;
        const int hq  = q * 256;

        const float* src = seq + (size_t)b * Hh * Ss;
        float* dst = g_trans + (size_t)b * Ss * Hh;

        float acc[8] = {0, 0, 0, 0, 0, 0, 0, 0};  // ssq partials, sl = warp + 4j
        for (int hb = 0; hb < 8; hb++) {
            const int h0 = hq + hb * 32;
#pragma unroll
            for (int j = 0; j < 8; j++) {
                int hr = warp + j * 4;
                tile[hr][lane] = src[(size_t)(h0 + hr) * Ss + s0 + lane]; // coalesced in s
            }
            __syncthreads();
#pragma unroll
            for (int j = 0; j < 8; j++) {
                int sl = warp + j * 4;
                float v = tile[lane][sl];                                // pad-33: no conflicts
                dst[(size_t)(s0 + sl) * Hh + h0 + lane] = v;             // coalesced in h
                acc[j] = fmaf(v, v, acc[j]);
            }
            __syncthreads();            // tile reusable next hb
        }
        // One butterfly for all 8 sl partials (chains interleaved).
#pragma unroll
        for (int o = 16; o; o >>= 1) {
#pragma unroll
            for (int j = 0; j < 8; j++)
                acc[j] += __shfl_xor_sync(0xffffffffu, acc[j], o);
        }
        if (lane == 0) {
#pragma unroll
            for (int j = 0; j < 8; j++) {
                int sl = warp + 4 * j;
                g_ssp4[((bc & 63) * NCHUNK + c) * 128 + sl * 4 + q] = acc[j];
            }
        }
        __syncthreads();
        if (tid == 0) {
            __threadfence();
            atomicAdd(&g_flag[b * NCHUNK + c], 1);
        }
        return;
    }

    // ======================= scan role =======================
    float* sbuf  = sm;                    // [2][T_TILE*Hh]
    float* smask = sm + SB_FLOATS;        // [Ss+8]
    float* part  = smask + (Ss + 8);      // [2][8]

    const int b = blockIdx.x;
    const uint32_t sb_u32 = (uint32_t)__cvta_generic_to_shared(sbuf);
    const float* gsrc = g_trans + (size_t)b * Ss * Hh;
    const float* ssp_b = g_ssp4 + b * NCHUNK * 128;

    for (int i = tid; i < Ss; i += THREADS) smask[i] = mask_in[b * Ss + i];
    if (tid < 8) smask[Ss + tid] = 0.0f;            // lookahead pad

    float h[8];
    {
        float4 a = *(const float4*)(tree + b * Hh + tid * 4);
        float4 c = *(const float4*)(tree + b * Hh + 512 + tid * 4);
        h[0]=a.x; h[1]=a.y; h[2]=a.z; h[3]=a.w;
        h[4]=c.x; h[5]=c.y; h[6]=c.z; h[7]=c.w;
    }

    // Chunk 0: wait, fetch norm partials (lane <-> s), prefetch tile 0.
    wait_flag(b * NCHUNK);
    float4 p4n = *(const float4*)(ssp_b + lane * 4);
    {
#pragma unroll
        for (int i = 0; i < 8; i++) {
            int c = tid + i * THREADS;
            cpa16(sb_u32 + c * 16, gsrc + c * 4);
        }
        asm volatile("cp.async.commit_group;\n");
    }
    __syncthreads();     // smask visible

    int pp = 0;
    float rcur = 0.0f;                  // per-lane 1/||s|| for current chunk
    float mcur = smask[0], sinvcur = 0.0f;
    float4 s0, s1;

    for (int t = 0; t < Ss; t++) {
        const int sl = t & (T_TILE - 1);
        const int k  = t >> 2;
        if (sl == 0) {
            asm volatile("cp.async.wait_group 0;\n" ::: "memory");
            __syncthreads();                       // tile k visible; k-1 free
            const int nk = k + 1;
            if (nk < NTILES) {
                if ((nk & 7) == 0) {               // 4 steps before entering chunk cn
                    const int cn = nk >> 3;
                    wait_flag(b * NCHUNK + cn);
                    p4n = *(const float4*)(ssp_b + cn * 128 + lane * 4);
                }
                const float*   srcp = gsrc + (size_t)nk * T_TILE * Hh;
                const uint32_t d = sb_u32 + (uint32_t)((nk & 1) * T_TILE * Hh * 4);
#pragma unroll
                for (int i = 0; i < 8; i++) {
                    int c = tid + i * THREADS;
                    cpa16(d + c * 16, srcp + c * 4);
                }
                asm volatile("cp.async.commit_group;\n");
            }
            if ((k & 7) == 0) {                    // entering a chunk: consume p4n
                float ssq = (p4n.x + p4n.y) + (p4n.z + p4n.w);
                rcur = rsqrtf(fmaxf(ssq, 1e-30f));
                sinvcur = __shfl_sync(0xffffffffu, rcur, 0);   // s = 32c + 0
            }
            const float* sp = sbuf + (k & 1) * (T_TILE * Hh);
            s0 = *(const float4*)(sp + tid * 4);
            s1 = *(const float4*)(sp + 512 + tid * 4);
        }

        // One-step lookahead (LDS + SHFL latencies hidden under reductions).
        const float mnext    = smask[t + 1];
        const float sinvnext = __shfl_sync(0xffffffffu, rcur, (t + 1) & 31);
        const float* spn = sbuf + (k & 1) * (T_TILE * Hh) + (sl + 1) * Hh;

        if (mcur != 0.0f) {          // mask uniform across the block
            float sv[8] = {s0.x, s0.y, s0.z, s0.w, s1.x, s1.y, s1.z, s1.w};

            float d0 = 0.0f, d1 = 0.0f, q0 = 0.0f, q1 = 0.0f;
#pragma unroll
            for (int i = 0; i < 4; i++) {
                d0 = fmaf(h[i],     sv[i],     d0);
                d1 = fmaf(h[i + 4], sv[i + 4], d1);
                q0 = fmaf(h[i],     h[i],      q0);
                q1 = fmaf(h[i + 4], h[i + 4],  q1);
            }
            float dot = d0 + d1, hh = q0 + q1;
#pragma unroll
            for (int o = 16; o; o >>= 1) {         // 2 chains interleaved
                float td = __shfl_xor_sync(0xffffffffu, dot, o);
                float th = __shfl_xor_sync(0xffffffffu, hh,  o);
                dot += td;
                hh  += th;
            }

            // Prefetch next step's s BEFORE the barrier.
            if (sl != T_TILE - 1) {
                s0 = *(const float4*)(spn + tid * 4);
                s1 = *(const float4*)(spn + 512 + tid * 4);
            }

            if (lane == 0)
                *(float2*)(part + pp * 8 + warp * 2) = make_float2(dot, hh);
            __syncthreads();
            float4 w0 = *(const float4*)(part + pp * 8);
            float4 w1 = *(const float4*)(part + pp * 8 + 4);
            float D  = (w0.x + w0.z) + (w1.x + w1.z);
            float HH = (w0.y + w0.w) + (w1.y + w1.w);

            float ra = rsqrtf(fmaxf(HH, 1e-30f));
            float a  = 1.0f - (D * ra) * sinvcur;  // h*(1-cos) + s; eps never binds
#pragma unroll
            for (int i = 0; i < 8; i++)
                h[i] = fminf(fmaxf(fmaf(h[i], a, sv[i]), -1.0f), 1.0f);
            pp ^= 1;
        } else {
            // reference clips even when mask == 0
#pragma unroll
            for (int i = 0; i < 8; i++)
                h[i] = fminf(fmaxf(h[i], -1.0f), 1.0f);
            if (sl != T_TILE - 1) {
                s0 = *(const float4*)(spn + tid * 4);
                s1 = *(const float4*)(spn + 512 + tid * 4);
            }
        }

        mcur    = mnext;
        sinvcur = sinvnext;
    }

    float* o = out + b * Hh;
    *(float4*)(o + tid * 4)       = make_float4(h[0], h[1], h[2], h[3]);
    *(float4*)(o + 512 + tid * 4) = make_float4(h[4], h[5], h[6], h[7]);
}

// ---------------------------------------------------------------------------
extern "C" void kernel_launch(void* const* d_in, const int* in_sizes, int n_in,
                              void* d_out, int out_size) {
    const float* tree = (const float*)d_in[0];   // (B,H)
    const float* seq  = (const float*)d_in[1];   // (B,H,S)
    const float* mask = (const float*)d_in[2];   // (B,S)
    float* out = (float*)d_out;                  // (B,H)

    zero_flags_kernel<<<2, 512>>>();
    fused_kernel<<<SCAN_CTAS + TR_CTAS, THREADS>>>(tree, seq, mask, out);
}

// round 11
// speedup vs baseline: 1.2686x; 1.0102x over previous
#include <cuda_runtime.h>
#include <cstdint>

#define Bb 64
#define Hh 1024
#define Ss 512
#define THREADS 128
#define SCAN_CTAS Bb
#define NCHUNK 16                  // s-chunks of 32 steps
#define QUARTERS 4                 // h split per producer chunk
#define TR_CTAS (Bb * NCHUNK * QUARTERS)   // 4096

#define T_TILE 4
#define NTILES (Ss / T_TILE)       // 128
#define SB_FLOATS (2 * T_TILE * Hh)                 // 32 KB double buffer
#define SMEM_FLOATS (SB_FLOATS + (Ss + 8) + 64 + 16)

// Scratch: transposed seq [B][S][H]; norm partials [B][C][32][4]; flags [B*C].
__device__ float g_trans[(size_t)Bb * Ss * Hh];       // 128 MB
__device__ float g_ssp4[Bb * NCHUNK * 32 * QUARTERS]; // 512 KB
__device__ int   g_flag[Bb * NCHUNK];                 // target = QUARTERS; scan CTA resets

__device__ __forceinline__ void cpa16(uint32_t dst, const float* src) {
    asm volatile("cp.async.cg.shared.global [%0], [%1], 16;\n" :: "r"(dst), "l"(src));
}

__device__ __forceinline__ void wait_flag(int fi) {
    if (threadIdx.x == 0) {
        int v;
        asm volatile("ld.acquire.gpu.global.b32 %0, [%1];"
                     : "=r"(v) : "l"(g_flag + fi) : "memory");
        while (v < QUARTERS) {
            __nanosleep(64);
            asm volatile("ld.acquire.gpu.global.b32 %0, [%1];"
                         : "=r"(v) : "l"(g_flag + fi) : "memory");
        }
    }
    __syncthreads();
}

// ---------------------------------------------------------------------------
// bid 0..63   : scan CTA (batch b = bid)
// bid 64..    : producer CTA (b, chunk, quarter): transpose 32s x 256h
//               + 4-way h-partial of ||s||^2, then release the flag.
// ---------------------------------------------------------------------------
__global__ __launch_bounds__(THREADS, 1)
void fused_kernel(const float* __restrict__ tree,
                  const float* __restrict__ seq,
                  const float* __restrict__ mask_in,
                  float* __restrict__ out) {
    __shared__ float sm[SMEM_FLOATS];
    const int tid  = threadIdx.x;
    const int lane = tid & 31;
    const int warp = tid >> 5;

    if (blockIdx.x >= SCAN_CTAS) {
        // ======================= producer role =======================
        float (*tile)[33] = (float(*)[33])sm;     // 32x33 floats (4.2 KB)
        const int idx = blockIdx.x - SCAN_CTAS;   // chunk-major ordering
        const int q   = idx & 3;
        const int bc  = idx >> 2;                 // c*64 + b
        const int b   = bc & 63;
        const int c   = bc >> 6;
        const int s0  = c * 32;
        const int hq  = q * 256;

        const float* src = seq + (size_t)b * Hh * Ss;
        float* dst = g_trans + (size_t)b * Ss * Hh;

        float acc[8] = {0, 0, 0, 0, 0, 0, 0, 0};  // ssq partials, sl = warp + 4j
        for (int hb = 0; hb < 8; hb++) {
            const int h0 = hq + hb * 32;
#pragma unroll
            for (int j = 0; j < 8; j++) {
                int hr = warp + j * 4;
                tile[hr][lane] = src[(size_t)(h0 + hr) * Ss + s0 + lane]; // coalesced in s
            }
            __syncthreads();
#pragma unroll
            for (int j = 0; j < 8; j++) {
                int sl = warp + j * 4;
                float v = tile[lane][sl];                                // pad-33: no conflicts
                dst[(size_t)(s0 + sl) * Hh + h0 + lane] = v;             // coalesced in h
                acc[j] = fmaf(v, v, acc[j]);
            }
            __syncthreads();            // tile reusable next hb
        }
        // One butterfly for all 8 sl partials (chains interleaved).
#pragma unroll
        for (int o = 16; o; o >>= 1) {
#pragma unroll
            for (int j = 0; j < 8; j++)
                acc[j] += __shfl_xor_sync(0xffffffffu, acc[j], o);
        }
        if (lane == 0) {
#pragma unroll
            for (int j = 0; j < 8; j++) {
                int sl = warp + 4 * j;
                g_ssp4[(b * NCHUNK + c) * 128 + sl * 4 + q] = acc[j];
            }
        }
        __syncthreads();
        if (tid == 0) {
            __threadfence();
            atomicAdd(&g_flag[b * NCHUNK + c], 1);
        }
        return;
    }

    // ======================= scan role =======================
    float* sbuf  = sm;                    // [2][T_TILE*Hh]
    float* smask = sm + SB_FLOATS;        // [Ss+8]
    float* part  = smask + (Ss + 8);      // [2][32] : 16 float2 (dot,hh) per buffer

    const int b = blockIdx.x;
    const uint32_t sb_u32 = (uint32_t)__cvta_generic_to_shared(sbuf);
    const float* gsrc = g_trans + (size_t)b * Ss * Hh;
    const float* ssp_b = g_ssp4 + b * NCHUNK * 128;

    for (int i = tid; i < Ss; i += THREADS) smask[i] = mask_in[b * Ss + i];
    if (tid < 8) smask[Ss + tid] = 0.0f;            // lookahead pad

    float h[8];
    {
        float4 a = *(const float4*)(tree + b * Hh + tid * 4);
        float4 c = *(const float4*)(tree + b * Hh + 512 + tid * 4);
        h[0]=a.x; h[1]=a.y; h[2]=a.z; h[3]=a.w;
        h[4]=c.x; h[5]=c.y; h[6]=c.z; h[7]=c.w;
    }

    // Chunk 0: wait, fetch norm partials (lane <-> s), prefetch tile 0.
    wait_flag(b * NCHUNK);
    float4 p4n = *(const float4*)(ssp_b + lane * 4);
    {
#pragma unroll
        for (int i = 0; i < 8; i++) {
            int c = tid + i * THREADS;
            cpa16(sb_u32 + c * 16, gsrc + c * 4);
        }
        asm volatile("cp.async.commit_group;\n");
    }
    __syncthreads();     // smask visible

    int pp = 0;
    float rcur = 0.0f;                  // per-lane 1/||s|| for current chunk
    float mcur = smask[0], sinvcur = 0.0f;
    float4 s0, s1;

    for (int t = 0; t < Ss; t++) {
        const int sl = t & (T_TILE - 1);
        const int k  = t >> 2;
        if (sl == 0) {
            asm volatile("cp.async.wait_group 0;\n" ::: "memory");
            __syncthreads();                       // tile k visible; k-1 free
            const int nk = k + 1;
            if (nk < NTILES) {
                if ((nk & 7) == 0) {               // 4 steps before entering chunk cn
                    const int cn = nk >> 3;
                    wait_flag(b * NCHUNK + cn);
                    p4n = *(const float4*)(ssp_b + cn * 128 + lane * 4);
                }
                const float*   srcp = gsrc + (size_t)nk * T_TILE * Hh;
                const uint32_t d = sb_u32 + (uint32_t)((nk & 1) * T_TILE * Hh * 4);
#pragma unroll
                for (int i = 0; i < 8; i++) {
                    int c = tid + i * THREADS;
                    cpa16(d + c * 16, srcp + c * 4);
                }
                asm volatile("cp.async.commit_group;\n");
            }
            if ((k & 7) == 0) {                    // entering a chunk: consume p4n
                float ssq = (p4n.x + p4n.y) + (p4n.z + p4n.w);
                rcur = rsqrtf(fmaxf(ssq, 1e-30f));
                sinvcur = __shfl_sync(0xffffffffu, rcur, 0);   // s = 32c + 0
            }
            const float* sp = sbuf + (k & 1) * (T_TILE * Hh);
            s0 = *(const float4*)(sp + tid * 4);
            s1 = *(const float4*)(sp + 512 + tid * 4);
        }

        // One-step lookahead (LDS + SHFL latencies hidden under reductions).
        const float mnext    = smask[t + 1];
        const float sinvnext = __shfl_sync(0xffffffffu, rcur, (t + 1) & 31);
        const float* spn = sbuf + (k & 1) * (T_TILE * Hh) + (sl + 1) * Hh;

        if (mcur != 0.0f) {          // mask uniform across the block
            float sv[8] = {s0.x, s0.y, s0.z, s0.w, s1.x, s1.y, s1.z, s1.w};

            float d0 = 0.0f, d1 = 0.0f, q0 = 0.0f, q1 = 0.0f;
#pragma unroll
            for (int i = 0; i < 4; i++) {
                d0 = fmaf(h[i],     sv[i],     d0);
                d1 = fmaf(h[i + 4], sv[i + 4], d1);
                q0 = fmaf(h[i],     h[i],      q0);
                q1 = fmaf(h[i + 4], h[i + 4],  q1);
            }
            float dot = d0 + d1, hh = q0 + q1;
            // 3-level butterfly only (chains interleaved): lanes 0-3 end up
            // holding 4 distinct 8-lane partial pairs per warp.
#pragma unroll
            for (int o = 16; o >= 4; o >>= 1) {
                float td = __shfl_xor_sync(0xffffffffu, dot, o);
                float th = __shfl_xor_sync(0xffffffffu, hh,  o);
                dot += td;
                hh  += th;
            }

            // Prefetch next step's s BEFORE the barrier.
            if (sl != T_TILE - 1) {
                s0 = *(const float4*)(spn + tid * 4);
                s1 = *(const float4*)(spn + 512 + tid * 4);
            }

            // 16 lanes (0-3 of each warp) publish their partial pair.
            if (lane < 4)
                *(float2*)(part + pp * 32 + (warp * 4 + lane) * 2)
                    = make_float2(dot, hh);
            __syncthreads();
            // Every thread reads all 16 pairs (8 broadcast LDS.128, pipelined)
            // and tree-sums them. Shorter chain than 2 more butterfly levels
            // + narrow combine.
            const float4* pw = (const float4*)(part + pp * 32);
            float4 w0 = pw[0], w1 = pw[1], w2 = pw[2], w3 = pw[3];
            float4 w4 = pw[4], w5 = pw[5], w6 = pw[6], w7 = pw[7];
            float Da = (w0.x + w0.z) + (w1.x + w1.z);
            float Db = (w2.x + w2.z) + (w3.x + w3.z);
            float Dc = (w4.x + w4.z) + (w5.x + w5.z);
            float Dd = (w6.x + w6.z) + (w7.x + w7.z);
            float Ha = (w0.y + w0.w) + (w1.y + w1.w);
            float Hb = (w2.y + w2.w) + (w3.y + w3.w);
            float Hc = (w4.y + w4.w) + (w5.y + w5.w);
            float Hd = (w6.y + w6.w) + (w7.y + w7.w);
            float D  = (Da + Db) + (Dc + Dd);
            float HH = (Ha + Hb) + (Hc + Hd);

            float ra = rsqrtf(fmaxf(HH, 1e-30f));
            float a  = 1.0f - (D * ra) * sinvcur;  // h*(1-cos) + s; eps never binds
#pragma unroll
            for (int i = 0; i < 8; i++)
                h[i] = fminf(fmaxf(fmaf(h[i], a, sv[i]), -1.0f), 1.0f);
            pp ^= 1;
        } else {
            // reference clips even when mask == 0
#pragma unroll
            for (int i = 0; i < 8; i++)
                h[i] = fminf(fmaxf(h[i], -1.0f), 1.0f);
            if (sl != T_TILE - 1) {
                s0 = *(const float4*)(spn + tid * 4);
                s1 = *(const float4*)(spn + 512 + tid * 4);
            }
        }

        mcur    = mnext;
        sinvcur = sinvnext;
    }

    float* o = out + b * Hh;
    *(float4*)(o + tid * 4)       = make_float4(h[0], h[1], h[2], h[3]);
    *(float4*)(o + 512 + tid * 4) = make_float4(h[4], h[5], h[6], h[7]);

    // Reset this batch's flags for the next graph replay (all producer
    // atomicAdds for batch b happened-before flag==QUARTERS, which
    // happened-before this point). Replaces the separate zeroing kernel.
    if (tid < NCHUNK) g_flag[b * NCHUNK + tid] = 0;
}

// ---------------------------------------------------------------------------
extern "C" void kernel_launch(void* const* d_in, const int* in_sizes, int n_in,
                              void* d_out, int out_size) {
    const float* tree = (const float*)d_in[0];   // (B,H)
    const float* seq  = (const float*)d_in[1];   // (B,H,S)
    const float* mask = (const float*)d_in[2];   // (B,S)
    float* out = (float*)d_out;                  // (B,H)

    fused_kernel<<<SCAN_CTAS + TR_CTAS, THREADS>>>(tree, seq, mask, out);
}

// round 13
// speedup vs baseline: 1.3192x; 1.0399x over previous
#include <cuda_runtime.h>
#include <cstdint>

#define Bb 64
#define Hh 1024
#define Ss 512
#define THREADS 128
#define SCAN_CTAS Bb
#define NCHUNK 16                  // s-chunks of 32 steps
#define QUARTERS 4                 // h split per producer chunk
#define TR_CTAS (Bb * NCHUNK * QUARTERS)   // 4096

#define T_TILE 8
#define NTILES (Ss / T_TILE)       // 64
#define SB_FLOATS (2 * T_TILE * Hh)                 // 16384 floats = 64 KB
#define SMEM_FLOATS (SB_FLOATS + (Ss + 8) + 64 + 8)
#define SMEM_BYTES (SMEM_FLOATS * 4)                // ~69.9 KB -> dynamic smem

// Scratch: transposed seq [B][S][H]; norm partials [B][C][32][4]; flags [B*C].
__device__ float g_trans[(size_t)Bb * Ss * Hh];       // 128 MB
__device__ float g_ssp4[Bb * NCHUNK * 32 * QUARTERS]; // 512 KB
__device__ int   g_flag[Bb * NCHUNK];                 // target = QUARTERS; scan CTA resets

__device__ __forceinline__ void cpa16(uint32_t dst, const float* src) {
    asm volatile("cp.async.cg.shared.global [%0], [%1], 16;\n" :: "r"(dst), "l"(src));
}

__device__ __forceinline__ void wait_flag(int fi) {
    if (threadIdx.x == 0) {
        int v;
        asm volatile("ld.acquire.gpu.global.b32 %0, [%1];"
                     : "=r"(v) : "l"(g_flag + fi) : "memory");
        while (v < QUARTERS) {
            __nanosleep(64);
            asm volatile("ld.acquire.gpu.global.b32 %0, [%1];"
                         : "=r"(v) : "l"(g_flag + fi) : "memory");
        }
    }
    __syncthreads();
}

// ---------------------------------------------------------------------------
// bid 0..63   : scan CTA (batch b = bid)
// bid 64..    : producer CTA (b, chunk, quarter): transpose 32s x 256h
//               + 4-way h-partial of ||s||^2, then release the flag.
// ---------------------------------------------------------------------------
__global__ __launch_bounds__(THREADS, 1)
void fused_kernel(const float* __restrict__ tree,
                  const float* __restrict__ seq,
                  const float* __restrict__ mask_in,
                  float* __restrict__ out) {
    extern __shared__ float smf[];
    const int tid  = threadIdx.x;
    const int lane = tid & 31;
    const int warp = tid >> 5;

    if (blockIdx.x >= SCAN_CTAS) {
        // ======================= producer role =======================
        float (*tile)[33] = (float(*)[33])smf;    // 32x33 floats (4.2 KB)
        const int idx = blockIdx.x - SCAN_CTAS;   // chunk-major ordering
        const int q   = idx & 3;
        const int bc  = idx >> 2;                 // c*64 + b
        const int b   = bc & 63;
        const int c   = bc >> 6;
        const int s0  = c * 32;
        const int hq  = q * 256;

        const float* src = seq + (size_t)b * Hh * Ss;
        float* dst = g_trans + (size_t)b * Ss * Hh;

        float acc[8] = {0, 0, 0, 0, 0, 0, 0, 0};  // ssq partials, sl = warp + 4j
        for (int hb = 0; hb < 8; hb++) {
            const int h0 = hq + hb * 32;
#pragma unroll
            for (int j = 0; j < 8; j++) {
                int hr = warp + j * 4;
                tile[hr][lane] = src[(size_t)(h0 + hr) * Ss + s0 + lane]; // coalesced in s
            }
            __syncthreads();
#pragma unroll
            for (int j = 0; j < 8; j++) {
                int sl = warp + j * 4;
                float v = tile[lane][sl];                                // pad-33: no conflicts
                dst[(size_t)(s0 + sl) * Hh + h0 + lane] = v;             // coalesced in h
                acc[j] = fmaf(v, v, acc[j]);
            }
            __syncthreads();            // tile reusable next hb
        }
        // One butterfly for all 8 sl partials (chains interleaved).
#pragma unroll
        for (int o = 16; o; o >>= 1) {
#pragma unroll
            for (int j = 0; j < 8; j++)
                acc[j] += __shfl_xor_sync(0xffffffffu, acc[j], o);
        }
        if (lane == 0) {
#pragma unroll
            for (int j = 0; j < 8; j++) {
                int sl = warp + 4 * j;
                g_ssp4[(b * NCHUNK + c) * 128 + sl * 4 + q] = acc[j];
            }
        }
        __syncthreads();
        if (tid == 0) {
            __threadfence();
            atomicAdd(&g_flag[b * NCHUNK + c], 1);
        }
        return;
    }

    // ======================= scan role =======================
    float* sbuf  = smf;                   // [2][T_TILE*Hh]  (64 KB)
    float* smask = smf + SB_FLOATS;       // [Ss+8]
    float* part  = smask + (Ss + 8);      // [2][32] : 16 float2 (dot,hh) per buffer

    const int b = blockIdx.x;
    const uint32_t sb_u32 = (uint32_t)__cvta_generic_to_shared(sbuf);
    const float* gsrc = g_trans + (size_t)b * Ss * Hh;
    const float* ssp_b = g_ssp4 + b * NCHUNK * 128;

    for (int i = tid; i < Ss; i += THREADS) smask[i] = mask_in[b * Ss + i];
    if (tid < 8) smask[Ss + tid] = 0.0f;            // lookahead pad

    float h[8];
    {
        float4 a = *(const float4*)(tree + b * Hh + tid * 4);
        float4 c = *(const float4*)(tree + b * Hh + 512 + tid * 4);
        h[0]=a.x; h[1]=a.y; h[2]=a.z; h[3]=a.w;
        h[4]=c.x; h[5]=c.y; h[6]=c.z; h[7]=c.w;
    }

    // Chunk 0: wait, fetch norm partials (lane <-> s), prefetch tile 0 (8 steps).
    wait_flag(b * NCHUNK);
    float4 p4n = *(const float4*)(ssp_b + lane * 4);
    {
#pragma unroll
        for (int i = 0; i < 16; i++) {
            int c = tid + i * THREADS;               // 2048 x 16B chunks
            cpa16(sb_u32 + c * 16, gsrc + c * 4);
        }
        asm volatile("cp.async.commit_group;\n");
    }
    __syncthreads();     // smask visible

    int pp = 0;
    float rcur = 0.0f;                  // per-lane 1/||s|| for current chunk
    float mcur = smask[0], sinvcur = 0.0f;
    float4 s0, s1;

    for (int t = 0; t < Ss; t++) {
        const int sl = t & (T_TILE - 1);
        const int k  = t >> 3;
        if (sl == 0) {
            asm volatile("cp.async.wait_group 0;\n" ::: "memory");
            __syncthreads();                       // tile k visible; k-1 free
            const int nk = k + 1;
            if (nk < NTILES) {
                if ((nk & 3) == 0) {               // 8 steps before entering chunk cn
                    const int cn = nk >> 2;
                    wait_flag(b * NCHUNK + cn);
                    p4n = *(const float4*)(ssp_b + cn * 128 + lane * 4);
                }
                const float*   srcp = gsrc + (size_t)nk * T_TILE * Hh;
                const uint32_t d = sb_u32 + (uint32_t)((nk & 1) * T_TILE * Hh * 4);
#pragma unroll
                for (int i = 0; i < 16; i++) {
                    int c = tid + i * THREADS;
                    cpa16(d + c * 16, srcp + c * 4);
                }
                asm volatile("cp.async.commit_group;\n");
            }
            if ((k & 3) == 0) {                    // entering a chunk: consume p4n
                float ssq = (p4n.x + p4n.y) + (p4n.z + p4n.w);
                rcur = rsqrtf(fmaxf(ssq, 1e-30f));
                sinvcur = __shfl_sync(0xffffffffu, rcur, 0);   // s = 32c + 0
            }
            const float* sp = sbuf + (k & 1) * (T_TILE * Hh);
            s0 = *(const float4*)(sp + tid * 4);
            s1 = *(const float4*)(sp + 512 + tid * 4);
        }

        // One-step lookahead (LDS + SHFL latencies hidden under reductions).
        const float mnext    = smask[t + 1];
        const float sinvnext = __shfl_sync(0xffffffffu, rcur, (t + 1) & 31);
        const float* spn = sbuf + (k & 1) * (T_TILE * Hh) + (sl + 1) * Hh;

        if (mcur != 0.0f) {          // mask uniform across the block
            float sv[8] = {s0.x, s0.y, s0.z, s0.w, s1.x, s1.y, s1.z, s1.w};

            float d0 = 0.0f, d1 = 0.0f, q0 = 0.0f, q1 = 0.0f;
#pragma unroll
            for (int i = 0; i < 4; i++) {
                d0 = fmaf(h[i],     sv[i],     d0);
                d1 = fmaf(h[i + 4], sv[i + 4], d1);
                q0 = fmaf(h[i],     h[i],      q0);
                q1 = fmaf(h[i + 4], h[i + 4],  q1);
            }
            float dot = d0 + d1, hh = q0 + q1;
            // 3-level butterfly (chains interleaved): lanes 0-3 keep
            // 8-lane partial pairs.
#pragma unroll
            for (int o = 16; o >= 4; o >>= 1) {
                float td = __shfl_xor_sync(0xffffffffu, dot, o);
                float th = __shfl_xor_sync(0xffffffffu, hh,  o);
                dot += td;
                hh  += th;
            }

            // Prefetch next step's s BEFORE the barrier.
            if (sl != T_TILE - 1) {
                s0 = *(const float4*)(spn + tid * 4);
                s1 = *(const float4*)(spn + 512 + tid * 4);
            }

            // 16 lanes (0-3 of each warp) publish their partial pair.
            if (lane < 4)
                *(float2*)(part + pp * 32 + (warp * 4 + lane) * 2)
                    = make_float2(dot, hh);
            __syncthreads();
            // Every thread reads all 16 pairs (8 broadcast LDS.128) and
            // tree-sums them.
            const float4* pw = (const float4*)(part + pp * 32);
            float4 w0 = pw[0], w1 = pw[1], w2 = pw[2], w3 = pw[3];
            float4 w4 = pw[4], w5 = pw[5], w6 = pw[6], w7 = pw[7];
            float Da = (w0.x + w0.z) + (w1.x + w1.z);
            float Db = (w2.x + w2.z) + (w3.x + w3.z);
            float Dc = (w4.x + w4.z) + (w5.x + w5.z);
            float Dd = (w6.x + w6.z) + (w7.x + w7.z);
            float Ha = (w0.y + w0.w) + (w1.y + w1.w);
            float Hb = (w2.y + w2.w) + (w3.y + w3.w);
            float Hc = (w4.y + w4.w) + (w5.y + w5.w);
            float Hd = (w6.y + w6.w) + (w7.y + w7.w);
            float D  = (Da + Db) + (Dc + Dd);
            float HH = (Ha + Hb) + (Hc + Hd);

            float ra = rsqrtf(fmaxf(HH, 1e-30f));
            float a  = 1.0f - (D * ra) * sinvcur;  // h*(1-cos) + s; eps never binds
#pragma unroll
            for (int i = 0; i < 8; i++)
                h[i] = fminf(fmaxf(fmaf(h[i], a, sv[i]), -1.0f), 1.0f);
            pp ^= 1;
        } else {
            // reference clips even when mask == 0
#pragma unroll
            for (int i = 0; i < 8; i++)
                h[i] = fminf(fmaxf(h[i], -1.0f), 1.0f);
            if (sl != T_TILE - 1) {
                s0 = *(const float4*)(spn + tid * 4);
                s1 = *(const float4*)(spn + 512 + tid * 4);
            }
        }

        mcur    = mnext;
        sinvcur = sinvnext;
    }

    float* o = out + b * Hh;
    *(float4*)(o + tid * 4)       = make_float4(h[0], h[1], h[2], h[3]);
    *(float4*)(o + 512 + tid * 4) = make_float4(h[4], h[5], h[6], h[7]);

    // Reset this batch's flags for the next graph replay (all producer
    // atomicAdds for batch b happened-before flag==QUARTERS, which
    // happened-before this point).
    if (tid < NCHUNK) g_flag[b * NCHUNK + tid] = 0;
}

// ---------------------------------------------------------------------------
extern "C" void kernel_launch(void* const* d_in, const int* in_sizes, int n_in,
                              void* d_out, int out_size) {
    const float* tree = (const float*)d_in[0];   // (B,H)
    const float* seq  = (const float*)d_in[1];   // (B,H,S)
    const float* mask = (const float*)d_in[2];   // (B,S)
    float* out = (float*)d_out;                  // (B,H)

    cudaFuncSetAttribute(fused_kernel,
                         cudaFuncAttributeMaxDynamicSharedMemorySize, SMEM_BYTES);
    fused_kernel<<<SCAN_CTAS + TR_CTAS, THREADS, SMEM_BYTES>>>(tree, seq, mask, out);
}